// round 10
// baseline (speedup 1.0000x reference)
#include <cuda_runtime.h>
#include <cuda_fp16.h>
#include <math.h>

// Problem constants
constexpr int kNQ = 8192;
constexpr int kNT = 8192;
constexpr int kD  = 128;
constexpr int kEC = 262144;
constexpr int kEQ = 262144;
constexpr int kET = 262144;

constexpr size_t SZ = (size_t)kNQ * kD;

// ---- scratch layout (float slots) ----
constexpr size_t O_HQ_AC = 0;              // half Xq_ac
constexpr size_t O_HT_AC = 1*SZ;           // half Xt_ac
constexpr size_t O_HQ_VC = 2*SZ;           // half Xq_vc
constexpr size_t O_XT_VC = 3*SZ;           // fp32 Xt_vc
constexpr size_t O_ACC   = 4*SZ;           // normalized Xq2t (written densely by cross_agg)
constexpr size_t O_XQM   = 5*SZ;
constexpr size_t O_XTM   = 6*SZ;
constexpr size_t O_HPS_T = 7*SZ;           // half Ps_T
constexpr size_t O_PD_T  = 8*SZ;
constexpr size_t O_HPS_Q = 9*SZ;           // half Ps_Q
constexpr size_t O_PD_Q  = 10*SZ;
// CSR sorted-src arrays (ints)
constexpr size_t O_SRT_C = 11*SZ;
constexpr size_t O_SRT_T = O_SRT_C + kEC;
constexpr size_t O_SRT_Q = O_SRT_T + kET;
// zero-init block
constexpr size_t O_DEGC  = O_SRT_Q + kEQ;
constexpr size_t O_DEGT  = O_DEGC + kNT;
constexpr size_t O_DEGQ  = O_DEGT + kNT;
constexpr size_t O_CNTQ  = O_DEGQ + kNQ;   // csrc histogram (t2q mask)
constexpr size_t O_QSUM  = O_CNTQ + kNQ;
constexpr size_t O_ZEND  = O_QSUM + kD;
// non-zeroed
constexpr size_t O_OFFC  = O_ZEND;
constexpr size_t O_CURC  = O_OFFC + kNT;
constexpr size_t O_OFFT  = O_CURC + kNT;
constexpr size_t O_CURT  = O_OFFT + kNT;
constexpr size_t O_OFFQ  = O_CURT + kNT;
constexpr size_t O_CURQ  = O_OFFQ + kNQ;
constexpr size_t O_SSRC_T= O_CURQ + kNQ;
constexpr size_t O_SDST_T= O_SSRC_T + kNT;
constexpr size_t O_SSRC_Q= O_SDST_T + kNT;
constexpr size_t O_SDST_Q= O_SSRC_Q + kNQ;
constexpr size_t O_BIAS  = O_SDST_Q + kNQ;
constexpr size_t O_TOTAL = O_BIAS + kD;

__device__ __align__(16) float g_scratch[O_TOTAL];

__device__ __forceinline__ float2 h2f(unsigned u) {
    __half2 h = *reinterpret_cast<__half2*>(&u);
    return __half22float2(h);
}

// ============================================================
// Tensor-core GEMM building blocks
// ============================================================
__device__ __forceinline__ void ldsm4(unsigned& r0, unsigned& r1, unsigned& r2, unsigned& r3,
                                      unsigned addr) {
    asm volatile("ldmatrix.sync.aligned.m8n8.x4.shared.b16 {%0,%1,%2,%3}, [%4];"
                 : "=r"(r0), "=r"(r1), "=r"(r2), "=r"(r3) : "r"(addr));
}
__device__ __forceinline__ void ldsm4t(unsigned& r0, unsigned& r1, unsigned& r2, unsigned& r3,
                                       unsigned addr) {
    asm volatile("ldmatrix.sync.aligned.m8n8.x4.trans.shared.b16 {%0,%1,%2,%3}, [%4];"
                 : "=r"(r0), "=r"(r1), "=r"(r2), "=r"(r3) : "r"(addr));
}
__device__ __forceinline__ void mma16816(float* c,
                                         unsigned a0, unsigned a1, unsigned a2, unsigned a3,
                                         unsigned b0, unsigned b1) {
    asm volatile("mma.sync.aligned.m16n8k16.row.col.f32.f16.f16.f32 "
                 "{%0,%1,%2,%3}, {%4,%5,%6,%7}, {%8,%9}, {%0,%1,%2,%3};"
                 : "+f"(c[0]), "+f"(c[1]), "+f"(c[2]), "+f"(c[3])
                 : "r"(a0), "r"(a1), "r"(a2), "r"(a3), "r"(b0), "r"(b1));
}

// ============================================================
// Batched HMMA GEMM: C[M,128] = act( [A0|A1][M,K] @ W[K,128] + bias )
// smode==2: mask A1 rows by (s1[r] > 0), s1 is int*.
// ============================================================
struct GemmJob {
    const float* A0; const float* A1;
    int K0; int K;
    const float* W; const float* bias;
    void* C; int act;
    const int* s1; int smode;
    int outHalf;
};
struct GemmBatch { GemmJob j[4]; };

constexpr int PA = 72;    // halves per A smem row (64 + 8 pad)
constexpr int PW = 136;   // halves per W smem row (128 + 8 pad)

__global__ void hgemm_b(const __grid_constant__ GemmBatch batch)
{
    const GemmJob& J = batch.j[blockIdx.y];

    __shared__ __half Asm[64 * PA];
    __shared__ __half Wsm[64 * PW];

    const int tid  = threadIdx.x;
    const int lane = tid & 31;
    const int wid  = tid >> 5;
    const int wm   = wid >> 1;
    const int wn   = wid & 1;
    const int m0   = blockIdx.x * 64;
    const int g    = lane >> 2, t = lane & 3;

    float acc[8][4];
    #pragma unroll
    for (int j = 0; j < 8; j++)
        #pragma unroll
        for (int i = 0; i < 4; i++) acc[j][i] = 0.f;

    const unsigned aBase = (unsigned)__cvta_generic_to_shared(Asm);
    const unsigned wBase = (unsigned)__cvta_generic_to_shared(Wsm);
    const unsigned aAddr = aBase + (((wm * 16 + (lane & 15)) * PA + ((lane >> 4) * 8)) << 1);
    const unsigned wAddr = wBase + (((lane & 15) * PW + wn * 64 + ((lane >> 4) * 8)) << 1);

    const int arow = tid >> 2;
    const int ac0  = (tid & 3) * 16;
    const int wc0  = (tid & 3) * 32;

    const int K = J.K, K0 = J.K0;
    for (int kc = 0; kc < K; kc += 64) {
        const bool inA1 = (kc >= K0);
        const float* Ap = inA1 ? J.A1 : J.A0;
        const int ldA   = inA1 ? (K - K0) : K0;
        const int kb    = inA1 ? (kc - K0) : kc;

        {
            float scale = 1.f;
            if (inA1 && J.smode == 2)
                scale = (J.s1[m0 + arow] > 0) ? 1.f : 0.f;
            const float* src = Ap + (size_t)(m0 + arow) * ldA + kb + ac0;
            __half* dst = Asm + arow * PA + ac0;
            #pragma unroll
            for (int i = 0; i < 4; i++) {
                float4 v = *reinterpret_cast<const float4*>(src + i * 4);
                __half2 h0 = __floats2half2_rn(v.x * scale, v.y * scale);
                __half2 h1 = __floats2half2_rn(v.z * scale, v.w * scale);
                uint2 o = {*reinterpret_cast<unsigned*>(&h0), *reinterpret_cast<unsigned*>(&h1)};
                *reinterpret_cast<uint2*>(dst + i * 4) = o;
            }
        }
        {
            const float* src = J.W + (size_t)(kc + arow) * 128 + wc0;
            __half* dst = Wsm + arow * PW + wc0;
            #pragma unroll
            for (int i = 0; i < 8; i++) {
                float4 v = *reinterpret_cast<const float4*>(src + i * 4);
                __half2 h0 = __floats2half2_rn(v.x, v.y);
                __half2 h1 = __floats2half2_rn(v.z, v.w);
                uint2 o = {*reinterpret_cast<unsigned*>(&h0), *reinterpret_cast<unsigned*>(&h1)};
                *reinterpret_cast<uint2*>(dst + i * 4) = o;
            }
        }
        __syncthreads();

        #pragma unroll
        for (int ks = 0; ks < 4; ks++) {
            unsigned a0, a1, a2, a3;
            ldsm4(a0, a1, a2, a3, aAddr + (ks * 16 << 1));
            #pragma unroll
            for (int nb = 0; nb < 4; nb++) {
                unsigned b0, b1, b2, b3;
                ldsm4t(b0, b1, b2, b3, wAddr + ((ks * 16 * PW + nb * 16) << 1));
                mma16816(acc[nb * 2],     a0, a1, a2, a3, b0, b1);
                mma16816(acc[nb * 2 + 1], a0, a1, a2, a3, b2, b3);
            }
        }
        __syncthreads();
    }

    const int rowA = m0 + wm * 16 + g;
    #pragma unroll
    for (int j = 0; j < 8; j++) {
        int col = wn * 64 + (j >> 1) * 16 + (j & 1) * 8 + t * 2;
        float b0 = 0.f, b1 = 0.f;
        if (J.bias) { b0 = J.bias[col]; b1 = J.bias[col + 1]; }
        float v00 = acc[j][0] + b0, v01 = acc[j][1] + b1;
        float v10 = acc[j][2] + b0, v11 = acc[j][3] + b1;
        if (J.act) {
            v00 = v00 > 0.f ? v00 : expm1f(v00);
            v01 = v01 > 0.f ? v01 : expm1f(v01);
            v10 = v10 > 0.f ? v10 : expm1f(v10);
            v11 = v11 > 0.f ? v11 : expm1f(v11);
        }
        if (J.outHalf) {
            __half2 h0 = __floats2half2_rn(v00, v01);
            __half2 h1 = __floats2half2_rn(v10, v11);
            *reinterpret_cast<__half2*>((__half*)J.C + (size_t)rowA * 128 + col) = h0;
            *reinterpret_cast<__half2*>((__half*)J.C + (size_t)(rowA + 8) * 128 + col) = h1;
        } else {
            float2 f0 = {v00, v01}, f1 = {v10, v11};
            *reinterpret_cast<float2*>((float*)J.C + (size_t)rowA * 128 + col) = f0;
            *reinterpret_cast<float2*>((float*)J.C + (size_t)(rowA + 8) * 128 + col) = f1;
        }
    }
}

__global__ void colsum_kernel(const float* __restrict__ X, float* __restrict__ sums)
{
    int j  = threadIdx.x;
    int r0 = blockIdx.x * 128;
    float s = 0.f;
    for (int r = 0; r < 128; r++) s += X[(size_t)(r0 + r) * kD + j];
    atomicAdd(&sums[j], s);
}

__global__ void bias_mt_kernel(const float* __restrict__ qsum, const float* __restrict__ W_mt,
                               const float* __restrict__ b_mt, float* __restrict__ be)
{
    int j = threadIdx.x;
    float s = b_mt[j];
    const float inv = 1.0f / (float)kNQ;
    for (int k = 0; k < kD; k++)
        s = fmaf(qsum[k] * inv, W_mt[(size_t)(256 + k) * kD + j], s);
    be[j] = s;
}

// ============================================================
// CSR build: histogram -> block scan -> scatter
// ============================================================
struct HJob { const int* idx; int* cnt; };
struct HBatch { HJob j[4]; };
__global__ void hist_b(const __grid_constant__ HBatch batch)
{
    const HJob& J = batch.j[blockIdx.y];
    int e = (blockIdx.x * blockDim.x + threadIdx.x) * 2;
    int2 d = *reinterpret_cast<const int2*>(J.idx + e);
    atomicAdd(&J.cnt[d.x], 1);
    atomicAdd(&J.cnt[d.y], 1);
}

struct SJob { const int* deg; int* off; int* cur; };
struct SBatch { SJob j[3]; };
__global__ void scan_b(const __grid_constant__ SBatch batch)
{
    const SJob& J = batch.j[blockIdx.x];
    int tid = threadIdx.x;                  // 256 threads x 32 elems -> 8192
    int base = tid * 32;
    int loc[32];
    int run = 0;
    #pragma unroll
    for (int k = 0; k < 32; k++) { loc[k] = run; run += J.deg[base + k]; }

    __shared__ int part[256];
    part[tid] = run;
    __syncthreads();
    int inc = run;
    for (int o = 1; o < 256; o <<= 1) {
        int t = (tid >= o) ? part[tid - o] : 0;
        __syncthreads();
        part[tid] += t;
        __syncthreads();
    }
    int excl = part[tid] - inc;
    #pragma unroll
    for (int k = 0; k < 32; k++) {
        int v = excl + loc[k];
        J.off[base + k] = v;
        J.cur[base + k] = v;
    }
}

struct ScJob { const int* src; const int* dst; int* cur; int* srt; };
struct ScBatch { ScJob j[3]; };
__global__ void scatter_b(const __grid_constant__ ScBatch batch)
{
    const ScJob& J = batch.j[blockIdx.y];
    int e = (blockIdx.x * blockDim.x + threadIdx.x) * 2;
    int2 s2 = *reinterpret_cast<const int2*>(J.src + e);
    int2 d2 = *reinterpret_cast<const int2*>(J.dst + e);
    int p0 = atomicAdd(&J.cur[d2.x], 1);
    J.srt[p0] = s2.x;
    int p1 = atomicAdd(&J.cur[d2.y], 1);
    J.srt[p1] = s2.y;
}

// ============================================================
// Cross aggregation: one warp per dst node v, 8 edges per iteration.
//   acc[v,:] = sum_e exp(dot(Aq[src_e], At[v])) * Vq[src_e,:] / denom  (0 if deg 0)
// Atomic-free, normalized output written once.
// ============================================================
__global__ void cross_agg(const int* __restrict__ srt, const int* __restrict__ off,
                          const int* __restrict__ deg,
                          const __half* __restrict__ Aq, const __half* __restrict__ At,
                          const __half* __restrict__ Vq,
                          float* __restrict__ accOut)
{
    int warp = (blockIdx.x * blockDim.x + threadIdx.x) >> 5;
    int lane = threadIdx.x & 31;
    int v = warp;

    int beg = off[v], dg = deg[v];
    int end = beg + dg;

    uint2 brow = *reinterpret_cast<const uint2*>(At + (size_t)v * kD + lane * 4);
    float2 b0 = h2f(brow.x), b1 = h2f(brow.y);

    float4 acc = {0.f, 0.f, 0.f, 0.f};
    float s = 0.f;

    for (int i = beg; i < end; i += 8) {
        int sl = 0;
        if (lane < 8) sl = srt[min(i + lane, end - 1)];
        int uu[8];
        #pragma unroll
        for (int k = 0; k < 8; k++) uu[k] = __shfl_sync(0xffffffffu, sl, k);

        uint2 a[8], vv[8];
        #pragma unroll
        for (int k = 0; k < 8; k++) {
            a[k]  = *reinterpret_cast<const uint2*>(Aq + (size_t)uu[k] * kD + lane * 4);
            vv[k] = *reinterpret_cast<const uint2*>(Vq + (size_t)uu[k] * kD + lane * 4);
        }

        float w[8];
        #pragma unroll
        for (int k = 0; k < 8; k++) {
            float2 a0 = h2f(a[k].x), a1 = h2f(a[k].y);
            w[k] = a0.x * b0.x + a0.y * b0.y + a1.x * b1.x + a1.y * b1.y;
        }
        #pragma unroll
        for (int o = 16; o; o >>= 1) {
            #pragma unroll
            for (int k = 0; k < 8; k++) w[k] += __shfl_xor_sync(0xffffffffu, w[k], o);
        }
        #pragma unroll
        for (int k = 0; k < 8; k++)
            w[k] = (i + k < end) ? expf(w[k]) : 0.f;

        #pragma unroll
        for (int k = 0; k < 8; k++) {
            s += w[k];
            float2 v0 = h2f(vv[k].x), v1 = h2f(vv[k].y);
            acc.x = fmaf(w[k], v0.x, acc.x);
            acc.y = fmaf(w[k], v0.y, acc.y);
            acc.z = fmaf(w[k], v1.x, acc.z);
            acc.w = fmaf(w[k], v1.y, acc.w);
        }
    }

    float r = (dg > 0) ? 1.f / s : 0.f;
    acc.x *= r; acc.y *= r; acc.z *= r; acc.w *= r;
    *reinterpret_cast<float4*>(accOut + (size_t)v * kD + lane * 4) = acc;
}

// batched per-node attention scalars
struct NsJob { const float* H; const float* Wa; const float* ba; float* ssrc; float* sdst; };
struct NsBatch { NsJob j[2]; };
__global__ void node_scalars_b(const __grid_constant__ NsBatch batch, int N)
{
    const NsJob& J = batch.j[blockIdx.y];
    int idx  = blockIdx.x * blockDim.x + threadIdx.x;
    int n    = idx >> 5;
    int lane = idx & 31;
    if (n >= N) return;
    float4 h  = *reinterpret_cast<const float4*>(J.H  + (size_t)n * kD + lane * 4);
    float4 w0 = *reinterpret_cast<const float4*>(J.Wa + lane * 4);
    float4 w1 = *reinterpret_cast<const float4*>(J.Wa + 128 + lane * 4);
    float p0 = h.x * w0.x + h.y * w0.y + h.z * w0.z + h.w * w0.w;
    float p1 = h.x * w1.x + h.y * w1.y + h.z * w1.z + h.w * w1.w;
    #pragma unroll
    for (int o = 16; o; o >>= 1) {
        p0 += __shfl_xor_sync(0xffffffffu, p0, o);
        p1 += __shfl_xor_sync(0xffffffffu, p1, o);
    }
    if (lane == 0) { J.ssrc[n] = p0; J.sdst[n] = p1 + J.ba[0]; }
}

// ============================================================
// Intra aggregation + finalize: one warp per dst node, 8 edges/iter.
//   out[v,:] = deg>0 ? (sum_e w_e * Ps[src_e,:]) / (sum w) + Pd[v,:] : 0
// ============================================================
struct IaJob { const int* srt; const int* off; const int* deg;
               const float* ssrc; const float* sdst;
               const __half* Ps; const float* Pd; float* out; };
struct IaBatch { IaJob j[2]; };
__global__ void intra_agg_b(const __grid_constant__ IaBatch batch)
{
    const IaJob& J = batch.j[blockIdx.y];
    int warp = (blockIdx.x * blockDim.x + threadIdx.x) >> 5;
    int lane = threadIdx.x & 31;
    int v = warp;

    int beg = J.off[v], dg = J.deg[v];
    int end = beg + dg;
    float sd = J.sdst[v];

    float4 acc = {0.f, 0.f, 0.f, 0.f};
    float s = 0.f;

    for (int i = beg; i < end; i += 8) {
        float wl = 0.f; int sl = 0;
        if (lane < 8) {
            int e = min(i + lane, end - 1);
            sl = J.srt[e];
            wl = (i + lane < end) ? expf(J.ssrc[sl] + sd) : 0.f;
        }
        int uu[8]; float wk[8];
        #pragma unroll
        for (int k = 0; k < 8; k++) {
            uu[k] = __shfl_sync(0xffffffffu, sl, k);
            wk[k] = __shfl_sync(0xffffffffu, wl, k);
        }
        uint2 vv[8];
        #pragma unroll
        for (int k = 0; k < 8; k++)
            vv[k] = *reinterpret_cast<const uint2*>(J.Ps + (size_t)uu[k] * kD + lane * 4);

        #pragma unroll
        for (int k = 0; k < 8; k++) {
            s += wk[k];
            float2 v0 = h2f(vv[k].x), v1 = h2f(vv[k].y);
            acc.x = fmaf(wk[k], v0.x, acc.x);
            acc.y = fmaf(wk[k], v0.y, acc.y);
            acc.z = fmaf(wk[k], v1.x, acc.z);
            acc.w = fmaf(wk[k], v1.y, acc.w);
        }
    }

    float4 o;
    if (dg > 0) {
        float4 pd = *reinterpret_cast<const float4*>(J.Pd + (size_t)v * kD + lane * 4);
        float r = 1.f / s;
        o.x = acc.x * r + pd.x;
        o.y = acc.y * r + pd.y;
        o.z = acc.z * r + pd.z;
        o.w = acc.w * r + pd.w;
    } else {
        o = {0.f, 0.f, 0.f, 0.f};
    }
    *reinterpret_cast<float4*>(J.out + (size_t)v * kD + lane * 4) = o;
}

// ============================================================
extern "C" void kernel_launch(void* const* d_in, const int* in_sizes, int n_in,
                              void* d_out, int out_size)
{
    (void)in_sizes; (void)n_in; (void)out_size;
    float* S = nullptr;
    cudaGetSymbolAddress((void**)&S, g_scratch);

    const float* Xq   = (const float*)d_in[0];
    const int*   eq   = (const int*)d_in[1];
    const float* Xt   = (const float*)d_in[2];
    const int*   et   = (const int*)d_in[3];
    const int*   csrc = (const int*)d_in[6];
    const int*   cdst = (const int*)d_in[7];

    const float* W_ac_q = (const float*)d_in[10]; const float* b_ac_q = (const float*)d_in[11];
    const float* W_ac_t = (const float*)d_in[12]; const float* b_ac_t = (const float*)d_in[13];
    const float* W_vc_q = (const float*)d_in[14]; const float* b_vc_q = (const float*)d_in[15];
    const float* W_vc_t = (const float*)d_in[16]; const float* b_vc_t = (const float*)d_in[17];
    const float* W_mq   = (const float*)d_in[18]; const float* b_mq   = (const float*)d_in[19];
    const float* W_mt   = (const float*)d_in[20]; const float* b_mt   = (const float*)d_in[21];
    const float* W_aq   = (const float*)d_in[22]; const float* b_aq   = (const float*)d_in[23];
    const float* W_vq   = (const float*)d_in[24]; const float* b_vq   = (const float*)d_in[25];
    const float* W_at   = (const float*)d_in[26]; const float* b_at   = (const float*)d_in[27];
    const float* W_vt   = (const float*)d_in[28]; const float* b_vt   = (const float*)d_in[29];

    float* outQ = (float*)d_out;
    float* outT = outQ + SZ;

    __half* HQ_AC = (__half*)(S + O_HQ_AC);
    __half* HT_AC = (__half*)(S + O_HT_AC);
    __half* HQ_VC = (__half*)(S + O_HQ_VC);
    __half* HPS_T = (__half*)(S + O_HPS_T);
    __half* HPS_Q = (__half*)(S + O_HPS_Q);

    int* DEGC = (int*)(S + O_DEGC); int* OFFC = (int*)(S + O_OFFC); int* CURC = (int*)(S + O_CURC);
    int* DEGT = (int*)(S + O_DEGT); int* OFFT = (int*)(S + O_OFFT); int* CURT = (int*)(S + O_CURT);
    int* DEGQ = (int*)(S + O_DEGQ); int* OFFQ = (int*)(S + O_OFFQ); int* CURQ = (int*)(S + O_CURQ);
    int* CNTQ = (int*)(S + O_CNTQ);
    int* SRTC = (int*)(S + O_SRT_C); int* SRTT = (int*)(S + O_SRT_T); int* SRTQ = (int*)(S + O_SRT_Q);

    // zero-init: deg/cnt/qsum block only
    cudaMemsetAsync(S + O_DEGC, 0, (O_ZEND - O_DEGC) * sizeof(float), 0);

    // ---- CSR build ----
    {
        HBatch b;
        b.j[0] = {cdst,      DEGC};
        b.j[1] = {csrc,      CNTQ};
        b.j[2] = {et + kET,  DEGT};
        b.j[3] = {eq + kEQ,  DEGQ};
        hist_b<<<dim3(kEC / 512, 4), 256>>>(b);
    }
    {
        SBatch b;
        b.j[0] = {DEGC, OFFC, CURC};
        b.j[1] = {DEGT, OFFT, CURT};
        b.j[2] = {DEGQ, OFFQ, CURQ};
        scan_b<<<3, 256>>>(b);
    }
    {
        ScBatch b;
        b.j[0] = {csrc, cdst,     CURC, SRTC};
        b.j[1] = {et,   et + kET, CURT, SRTT};
        b.j[2] = {eq,   eq + kEQ, CURQ, SRTQ};
        scatter_b<<<dim3(kEC / 512, 3), 256>>>(b);
    }

    // ---- stage 1: 4 ELU node transforms (HMMA) ----
    {
        GemmBatch b;
        b.j[0] = {Xq, nullptr, 128, 128, W_ac_q, b_ac_q, HQ_AC,       1, nullptr, 0, 1};
        b.j[1] = {Xt, nullptr, 128, 128, W_ac_t, b_ac_t, HT_AC,       1, nullptr, 0, 1};
        b.j[2] = {Xq, nullptr, 128, 128, W_vc_q, b_vc_q, HQ_VC,       1, nullptr, 0, 1};
        b.j[3] = {Xt, nullptr, 128, 128, W_vc_t, b_vc_t, S + O_XT_VC, 1, nullptr, 0, 0};
        hgemm_b<<<dim3(kNQ / 64, 4), 256>>>(b);
    }

    colsum_kernel<<<kNQ / 128, 128>>>(Xq, S + O_QSUM);
    bias_mt_kernel<<<1, 128>>>(S + O_QSUM, W_mt, b_mt, S + O_BIAS);

    // ---- cross aggregation (atomic-free, pre-normalized) ----
    cross_agg<<<kNT * 32 / 256, 256>>>(SRTC, OFFC, DEGC, HQ_AC, HT_AC, HQ_VC, S + O_ACC);

    // ---- stage 2: merged features (K=256) ----
    {
        GemmBatch b;
        b.j[0] = {Xq, S + O_XT_VC, 128, 256, W_mq, b_mq,       S + O_XQM, 0, CNTQ,    2, 0};
        b.j[1] = {Xt, S + O_ACC,   128, 256, W_mt, S + O_BIAS, S + O_XTM, 0, nullptr, 0, 0};
        b.j[2] = b.j[0]; b.j[3] = b.j[0];
        hgemm_b<<<dim3(kNQ / 64, 2), 256>>>(b);
    }

    // ---- stage 3: 4 intra projections ----
    {
        GemmBatch b;
        b.j[0] = {S + O_XTM, nullptr, 128, 128, W_vt,            nullptr, HPS_T,      0, nullptr, 0, 1};
        b.j[1] = {S + O_XTM, nullptr, 128, 128, W_vt + 128 * kD, b_vt,    S + O_PD_T, 0, nullptr, 0, 0};
        b.j[2] = {S + O_XQM, nullptr, 128, 128, W_vq,            nullptr, HPS_Q,      0, nullptr, 0, 1};
        b.j[3] = {S + O_XQM, nullptr, 128, 128, W_vq + 128 * kD, b_vq,    S + O_PD_Q, 0, nullptr, 0, 0};
        hgemm_b<<<dim3(kNQ / 64, 4), 256>>>(b);
    }

    {
        NsBatch b;
        b.j[0] = {S + O_XTM, W_at, b_at, S + O_SSRC_T, S + O_SDST_T};
        b.j[1] = {S + O_XQM, W_aq, b_aq, S + O_SSRC_Q, S + O_SDST_Q};
        node_scalars_b<<<dim3((kNT * 32) / 256, 2), 256>>>(b, kNT);
    }

    // ---- intra aggregation + finalize (atomic-free, both graphs) ----
    {
        IaBatch b;
        b.j[0] = {SRTT, OFFT, DEGT, S + O_SSRC_T, S + O_SDST_T, HPS_T, S + O_PD_T, outT};
        b.j[1] = {SRTQ, OFFQ, DEGQ, S + O_SSRC_Q, S + O_SDST_Q, HPS_Q, S + O_PD_Q, outQ};
        intra_agg_b<<<dim3(kNT * 32 / 256, 2), 256>>>(b);
    }
}

// round 11
// speedup vs baseline: 1.2232x; 1.2232x over previous
#include <cuda_runtime.h>
#include <cuda_fp16.h>
#include <math.h>

// Problem constants
constexpr int kNQ = 8192;
constexpr int kNT = 8192;
constexpr int kD  = 128;
constexpr int kEC = 262144;
constexpr int kEQ = 262144;
constexpr int kET = 262144;

constexpr size_t SZ = (size_t)kNQ * kD;

// ---- scratch layout (float slots) ----
constexpr size_t O_HQ_AC = 0;              // half Xq_ac
constexpr size_t O_HT_AC = 1*SZ;           // half Xt_ac
constexpr size_t O_HQ_VC = 2*SZ;           // half Xq_vc
constexpr size_t O_XT_VC = 3*SZ;           // fp32 Xt_vc
constexpr size_t O_ACC   = 4*SZ;           // unnormalized Xq2t accumulator (fp32)
constexpr size_t O_XQM   = 5*SZ;
constexpr size_t O_XTM   = 6*SZ;
constexpr size_t O_HPS_T = 7*SZ;           // half Ps_T
constexpr size_t O_PD_T  = 8*SZ;
constexpr size_t O_HPS_Q = 9*SZ;           // half Ps_Q
constexpr size_t O_PD_Q  = 10*SZ;
// zero-init scalar block
constexpr size_t O_SV    = 11*SZ;
constexpr size_t O_CNT   = O_SV + kNT;
constexpr size_t O_ST    = O_CNT + kNQ;
constexpr size_t O_SQ    = O_ST + kNT;
constexpr size_t O_QSUM  = O_SQ + kNQ;
constexpr size_t O_ZEND  = O_QSUM + kD;
// non-zeroed scalars
constexpr size_t O_SSRC_T= O_ZEND;
constexpr size_t O_SDST_T= O_SSRC_T + kNT;
constexpr size_t O_SSRC_Q= O_SDST_T + kNT;
constexpr size_t O_SDST_Q= O_SSRC_Q + kNQ;
constexpr size_t O_BIAS  = O_SDST_Q + kNQ;
// fp16 pre-converted weights (196608 halves = 98304 float slots)
constexpr size_t O_WH    = O_BIAS + kD;
constexpr size_t O_TOTAL = O_WH + 98304;

// half offsets inside the WH region
constexpr int WH_ACQ = 0;
constexpr int WH_ACT = 16384;
constexpr int WH_VCQ = 32768;
constexpr int WH_VCT = 49152;
constexpr int WH_MQ  = 65536;   // 256x128
constexpr int WH_MT  = 98304;   // 256x128 (rows 0-255 of W_mt)
constexpr int WH_VT  = 131072;  // 256x128
constexpr int WH_VQ  = 163840;  // 256x128

__device__ __align__(16) float g_scratch[O_TOTAL];

__device__ __forceinline__ float2 h2f(unsigned u) {
    __half2 h = *reinterpret_cast<__half2*>(&u);
    return __half22float2(h);
}

// ============================================================
// Tensor-core building blocks
// ============================================================
__device__ __forceinline__ void ldsm4(unsigned& r0, unsigned& r1, unsigned& r2, unsigned& r3,
                                      unsigned addr) {
    asm volatile("ldmatrix.sync.aligned.m8n8.x4.shared.b16 {%0,%1,%2,%3}, [%4];"
                 : "=r"(r0), "=r"(r1), "=r"(r2), "=r"(r3) : "r"(addr));
}
__device__ __forceinline__ void ldsm4t(unsigned& r0, unsigned& r1, unsigned& r2, unsigned& r3,
                                       unsigned addr) {
    asm volatile("ldmatrix.sync.aligned.m8n8.x4.trans.shared.b16 {%0,%1,%2,%3}, [%4];"
                 : "=r"(r0), "=r"(r1), "=r"(r2), "=r"(r3) : "r"(addr));
}
__device__ __forceinline__ void mma16816(float* c,
                                         unsigned a0, unsigned a1, unsigned a2, unsigned a3,
                                         unsigned b0, unsigned b1) {
    asm volatile("mma.sync.aligned.m16n8k16.row.col.f32.f16.f16.f32 "
                 "{%0,%1,%2,%3}, {%4,%5,%6,%7}, {%8,%9}, {%0,%1,%2,%3};"
                 : "+f"(c[0]), "+f"(c[1]), "+f"(c[2]), "+f"(c[3])
                 : "r"(a0), "r"(a1), "r"(a2), "r"(a3), "r"(b0), "r"(b1));
}
__device__ __forceinline__ void cp16(unsigned dst, const void* src) {
    asm volatile("cp.async.ca.shared.global [%0], [%1], 16;" :: "r"(dst), "l"(src));
}

// ============================================================
// Weight pre-conversion: fp32 -> fp16, batched jobs
// ============================================================
struct CvJob { const float* src; __half* dst; int n; };
struct CvBatch { CvJob j[8]; };
__global__ void convert_w_b(const __grid_constant__ CvBatch batch)
{
    const CvJob& J = batch.j[blockIdx.y];
    int i = (blockIdx.x * 256 + threadIdx.x) * 4;
    if (i >= J.n) return;
    float4 v = *reinterpret_cast<const float4*>(J.src + i);
    __half2 h0 = __floats2half2_rn(v.x, v.y);
    __half2 h1 = __floats2half2_rn(v.z, v.w);
    uint2 o = {*reinterpret_cast<unsigned*>(&h0), *reinterpret_cast<unsigned*>(&h1)};
    *reinterpret_cast<uint2*>(J.dst + i) = o;
}

// ============================================================
// Batched HMMA GEMM, double-buffered, BK=32, cp.async W staging.
// C[M,128] = act( [A0|A1][M,K] @ W[K,128] + bias ), W pre-converted fp16.
// smode on A1 rows: 1 -> *(1/s1[r]) (0 if s<=0), 2 -> mask(s1[r]>0).
// ============================================================
struct GemmJob {
    const float* A0; const float* A1;
    int K0; int K;
    const __half* W; const float* bias;
    void* C; int act;
    const float* s1; int smode;
    int outHalf;
};
struct GemmBatch { GemmJob j[4]; };

constexpr int PA = 40;    // halves per A smem row (32 + 8 pad) -> 80B pitch
constexpr int PW = 136;   // halves per W smem row (128 + 8 pad) -> 272B pitch
constexpr int ABUFB = 64 * PA * 2;   // bytes per A buffer (5120)
constexpr int WBUFB = 32 * PW * 2;   // bytes per W buffer (8704)

__global__ void hgemm_b(const __grid_constant__ GemmBatch batch)
{
    const GemmJob& J = batch.j[blockIdx.y];

    __shared__ __half Asm[2][64 * PA];
    __shared__ __half Wsm[2][32 * PW];

    const int tid  = threadIdx.x;
    const int lane = tid & 31;
    const int wid  = tid >> 5;
    const int wm   = wid >> 1;
    const int wn   = wid & 1;
    const int m0   = blockIdx.x * 64;
    const int g    = lane >> 2, t = lane & 3;

    float acc[8][4];
    #pragma unroll
    for (int j = 0; j < 8; j++)
        #pragma unroll
        for (int i = 0; i < 4; i++) acc[j][i] = 0.f;

    const unsigned aBase = (unsigned)__cvta_generic_to_shared(&Asm[0][0]);
    const unsigned wBase = (unsigned)__cvta_generic_to_shared(&Wsm[0][0]);
    const unsigned aOff = ((wm * 16 + (lane & 15)) * PA + ((lane >> 4) * 8)) << 1;
    const unsigned wOff = ((lane & 15) * PW + wn * 64 + ((lane >> 4) * 8)) << 1;

    // A load mapping: 64x32 fp32 chunk, 8 floats per thread
    const int arow = tid >> 2;
    const int acol = (tid & 3) * 8;
    // W cp.async mapping: 512 16B units, 2 per thread
    const int wr0 = tid >> 4,          wc8_0 = (tid & 15) * 8;
    const int wr1 = (tid + 256) >> 4,  wc8_1 = wc8_0;

    const int K = J.K, K0 = J.K0;
    const int nc = K / 32;

    float4 ra0, ra1; float scale = 1.f;

    auto issueW = [&](int c, int buf) {
        const __half* ws = J.W + (size_t)(c * 32) * 128;
        unsigned wd = wBase + buf * WBUFB;
        cp16(wd + ((wr0 * PW + wc8_0) << 1), ws + wr0 * 128 + wc8_0);
        cp16(wd + ((wr1 * PW + wc8_1) << 1), ws + wr1 * 128 + wc8_1);
        asm volatile("cp.async.commit_group;");
    };
    auto ldgA = [&](int c) {
        int kc = c * 32;
        bool inA1 = (kc >= K0);
        const float* Ap = inA1 ? J.A1 : J.A0;
        int ldA = inA1 ? (K - K0) : K0;
        int kb  = inA1 ? (kc - K0) : kc;
        const float* src = Ap + (size_t)(m0 + arow) * ldA + kb + acol;
        ra0 = *reinterpret_cast<const float4*>(src);
        ra1 = *reinterpret_cast<const float4*>(src + 4);
        scale = 1.f;
        if (inA1 && J.smode) {
            float sv = J.s1[m0 + arow];
            scale = (J.smode == 1) ? (sv > 0.f ? 1.f / sv : 0.f)
                                   : (sv > 0.f ? 1.f : 0.f);
        }
    };
    auto stsA = [&](int buf) {
        __half2 h0 = __floats2half2_rn(ra0.x * scale, ra0.y * scale);
        __half2 h1 = __floats2half2_rn(ra0.z * scale, ra0.w * scale);
        __half2 h2 = __floats2half2_rn(ra1.x * scale, ra1.y * scale);
        __half2 h3 = __floats2half2_rn(ra1.z * scale, ra1.w * scale);
        uint4 o = {*reinterpret_cast<unsigned*>(&h0), *reinterpret_cast<unsigned*>(&h1),
                   *reinterpret_cast<unsigned*>(&h2), *reinterpret_cast<unsigned*>(&h3)};
        *reinterpret_cast<uint4*>(&Asm[buf][arow * PA + acol]) = o;
    };

    // prologue: stage chunk 0
    issueW(0, 0);
    ldgA(0);
    stsA(0);
    asm volatile("cp.async.wait_group 0;");
    __syncthreads();

    for (int c = 0; c < nc; c++) {
        int cur = c & 1, nxt = cur ^ 1;
        bool more = (c + 1 < nc);
        if (more) {
            issueW(c + 1, nxt);
            ldgA(c + 1);
        }
        // mma on current buffer
        unsigned aA = aBase + cur * ABUFB + aOff;
        unsigned wA = wBase + cur * WBUFB + wOff;
        #pragma unroll
        for (int ks = 0; ks < 2; ks++) {
            unsigned a0, a1, a2, a3;
            ldsm4(a0, a1, a2, a3, aA + ks * 32);
            #pragma unroll
            for (int nb = 0; nb < 4; nb++) {
                unsigned b0, b1, b2, b3;
                ldsm4t(b0, b1, b2, b3, wA + ((ks * 16 * PW + nb * 16) << 1));
                mma16816(acc[nb * 2],     a0, a1, a2, a3, b0, b1);
                mma16816(acc[nb * 2 + 1], a0, a1, a2, a3, b2, b3);
            }
        }
        if (more) {
            stsA(nxt);
            asm volatile("cp.async.wait_group 0;");
        }
        __syncthreads();
    }

    // epilogue
    const int rowA = m0 + wm * 16 + g;
    #pragma unroll
    for (int j = 0; j < 8; j++) {
        int col = wn * 64 + (j >> 1) * 16 + (j & 1) * 8 + t * 2;
        float b0 = 0.f, b1 = 0.f;
        if (J.bias) { b0 = J.bias[col]; b1 = J.bias[col + 1]; }
        float v00 = acc[j][0] + b0, v01 = acc[j][1] + b1;
        float v10 = acc[j][2] + b0, v11 = acc[j][3] + b1;
        if (J.act) {
            v00 = v00 > 0.f ? v00 : expm1f(v00);
            v01 = v01 > 0.f ? v01 : expm1f(v01);
            v10 = v10 > 0.f ? v10 : expm1f(v10);
            v11 = v11 > 0.f ? v11 : expm1f(v11);
        }
        if (J.outHalf) {
            __half2 h0 = __floats2half2_rn(v00, v01);
            __half2 h1 = __floats2half2_rn(v10, v11);
            *reinterpret_cast<__half2*>((__half*)J.C + (size_t)rowA * 128 + col) = h0;
            *reinterpret_cast<__half2*>((__half*)J.C + (size_t)(rowA + 8) * 128 + col) = h1;
        } else {
            float2 f0 = {v00, v01}, f1 = {v10, v11};
            *reinterpret_cast<float2*>((float*)J.C + (size_t)rowA * 128 + col) = f0;
            *reinterpret_cast<float2*>((float*)J.C + (size_t)(rowA + 8) * 128 + col) = f1;
        }
    }
}

__global__ void colsum_kernel(const float* __restrict__ X, float* __restrict__ sums)
{
    int j  = threadIdx.x;
    int r0 = blockIdx.x * 128;
    float s = 0.f;
    for (int r = 0; r < 128; r++) s += X[(size_t)(r0 + r) * kD + j];
    atomicAdd(&sums[j], s);
}

__global__ void bias_mt_kernel(const float* __restrict__ qsum, const float* __restrict__ W_mt,
                               const float* __restrict__ b_mt, float* __restrict__ be)
{
    int j = threadIdx.x;
    float s = b_mt[j];
    const float inv = 1.0f / (float)kNQ;
    for (int k = 0; k < kD; k++)
        s = fmaf(qsum[k] * inv, W_mt[(size_t)(256 + k) * kD + j], s);
    be[j] = s;
}

// ============================================================
// Fused cross attention (R8 version: fp16 gathers, RED scatter)
// ============================================================
__global__ void cross_fused(const int* __restrict__ src, const int* __restrict__ dst,
                            const __half* __restrict__ Aq, const __half* __restrict__ At,
                            const __half* __restrict__ Vq,
                            float* __restrict__ s_v, float* __restrict__ cnt_u,
                            float* __restrict__ acc)
{
    int gtid = blockIdx.x * blockDim.x + threadIdx.x;
    int warp = gtid >> 5;
    int lane = gtid & 31;
    int e0 = warp * 4;

    int idxv = 0;
    if (lane < 8) {
        int e = e0 + (lane & 3);
        idxv = (lane < 4) ? src[e] : dst[e];
    }
    int uu[4], dd[4];
    #pragma unroll
    for (int k = 0; k < 4; k++) {
        uu[k] = __shfl_sync(0xffffffffu, idxv, k);
        dd[k] = __shfl_sync(0xffffffffu, idxv, 4 + k);
    }

    uint2 a[4], b[4], v[4];
    #pragma unroll
    for (int k = 0; k < 4; k++) {
        a[k] = *reinterpret_cast<const uint2*>(Aq + (size_t)uu[k] * kD + lane * 4);
        b[k] = *reinterpret_cast<const uint2*>(At + (size_t)dd[k] * kD + lane * 4);
        v[k] = *reinterpret_cast<const uint2*>(Vq + (size_t)uu[k] * kD + lane * 4);
    }

    float w[4];
    #pragma unroll
    for (int k = 0; k < 4; k++) {
        float2 a0 = h2f(a[k].x), a1 = h2f(a[k].y);
        float2 b0 = h2f(b[k].x), b1 = h2f(b[k].y);
        w[k] = a0.x * b0.x + a0.y * b0.y + a1.x * b1.x + a1.y * b1.y;
    }
    #pragma unroll
    for (int o = 16; o; o >>= 1) {
        #pragma unroll
        for (int k = 0; k < 4; k++) w[k] += __shfl_xor_sync(0xffffffffu, w[k], o);
    }
    #pragma unroll
    for (int k = 0; k < 4; k++) w[k] = expf(w[k]);

    {
        float wl = w[0]; int dl = dd[0], ul = uu[0];
        if (lane == 1) { wl = w[1]; dl = dd[1]; ul = uu[1]; }
        if (lane == 2) { wl = w[2]; dl = dd[2]; ul = uu[2]; }
        if (lane == 3) { wl = w[3]; dl = dd[3]; ul = uu[3]; }
        if (lane < 4) {
            atomicAdd(&s_v[dl], wl);
            atomicAdd(&cnt_u[ul], 1.0f);
        }
    }

    #pragma unroll
    for (int k = 0; k < 4; k++) {
        float2 v0 = h2f(v[k].x), v1 = h2f(v[k].y);
        float* p = acc + (size_t)dd[k] * kD + lane * 4;
        asm volatile("red.global.add.v4.f32 [%0], {%1,%2,%3,%4};"
                     :: "l"(p), "f"(w[k] * v0.x), "f"(w[k] * v0.y),
                        "f"(w[k] * v1.x), "f"(w[k] * v1.y)
                     : "memory");
    }
}

// batched per-node attention scalars (fp32 H)
struct NsJob { const float* H; const float* Wa; const float* ba; float* ssrc; float* sdst; };
struct NsBatch { NsJob j[2]; };
__global__ void node_scalars_b(const __grid_constant__ NsBatch batch, int N)
{
    const NsJob& J = batch.j[blockIdx.y];
    int idx  = blockIdx.x * blockDim.x + threadIdx.x;
    int n    = idx >> 5;
    int lane = idx & 31;
    if (n >= N) return;
    float4 h  = *reinterpret_cast<const float4*>(J.H  + (size_t)n * kD + lane * 4);
    float4 w0 = *reinterpret_cast<const float4*>(J.Wa + lane * 4);
    float4 w1 = *reinterpret_cast<const float4*>(J.Wa + 128 + lane * 4);
    float p0 = h.x * w0.x + h.y * w0.y + h.z * w0.z + h.w * w0.w;
    float p1 = h.x * w1.x + h.y * w1.y + h.z * w1.z + h.w * w1.w;
    #pragma unroll
    for (int o = 16; o; o >>= 1) {
        p0 += __shfl_xor_sync(0xffffffffu, p0, o);
        p1 += __shfl_xor_sync(0xffffffffu, p1, o);
    }
    if (lane == 0) { J.ssrc[n] = p0; J.sdst[n] = p1 + J.ba[0]; }
}

// ============================================================
// Fused intra attention, fp16 value gathers (R8 version)
// ============================================================
struct IfJob { const int* src; const int* dst; const float* ssrc; const float* sdst;
               const __half* Ps; float* s; float* out; };
struct IfBatch { IfJob j[2]; };
__global__ void intra_fused_b(const __grid_constant__ IfBatch batch, int E)
{
    const IfJob& J = batch.j[blockIdx.y];
    int gtid = blockIdx.x * blockDim.x + threadIdx.x;
    int warp = gtid >> 5;
    int lane = gtid & 31;
    int e0 = warp * 4;

    int sI = 0, dI = 0; float w = 0.f;
    if (lane < 4) {
        int e = e0 + lane;
        sI = J.src[e];
        dI = J.dst[e];
        w = expf(J.ssrc[sI] + J.sdst[dI]);
        atomicAdd(&J.s[dI], w);
    }

    int g[4], d[4]; float wk[4]; uint2 v[4];
    #pragma unroll
    for (int k = 0; k < 4; k++) {
        g[k]  = __shfl_sync(0xffffffffu, sI, k);
        d[k]  = __shfl_sync(0xffffffffu, dI, k);
        wk[k] = __shfl_sync(0xffffffffu, w,  k);
    }
    #pragma unroll
    for (int k = 0; k < 4; k++)
        v[k] = *reinterpret_cast<const uint2*>(J.Ps + (size_t)g[k] * kD + lane * 4);
    #pragma unroll
    for (int k = 0; k < 4; k++) {
        float2 v0 = h2f(v[k].x), v1 = h2f(v[k].y);
        float* p = J.out + (size_t)d[k] * kD + lane * 4;
        asm volatile("red.global.add.v4.f32 [%0], {%1,%2,%3,%4};"
                     :: "l"(p), "f"(wk[k] * v0.x), "f"(wk[k] * v0.y),
                        "f"(wk[k] * v1.x), "f"(wk[k] * v1.y)
                     : "memory");
    }
}

// batched finalize: out[n,:] = s[n] > 0 ? out[n,:]/s[n] + pd[n,:] : 0
struct FinJob { const float* s; const float* pd; float* out; };
struct FinBatch { FinJob j[2]; };
__global__ void finalize_b(const __grid_constant__ FinBatch batch)
{
    const FinJob& J = batch.j[blockIdx.y];
    size_t i4 = ((size_t)blockIdx.x * blockDim.x + threadIdx.x) * 4;
    int n = (int)(i4 >> 7);
    float sv = J.s[n];
    float4 o = *reinterpret_cast<float4*>(J.out + i4);
    float4 p = *reinterpret_cast<const float4*>(J.pd + i4);
    if (sv > 0.f) {
        float r = 1.f / sv;
        o.x = o.x * r + p.x;
        o.y = o.y * r + p.y;
        o.z = o.z * r + p.z;
        o.w = o.w * r + p.w;
    } else {
        o = {0.f, 0.f, 0.f, 0.f};
    }
    *reinterpret_cast<float4*>(J.out + i4) = o;
}

// ============================================================
extern "C" void kernel_launch(void* const* d_in, const int* in_sizes, int n_in,
                              void* d_out, int out_size)
{
    (void)in_sizes; (void)n_in; (void)out_size;
    float* S = nullptr;
    cudaGetSymbolAddress((void**)&S, g_scratch);

    const float* Xq   = (const float*)d_in[0];
    const int*   eq   = (const int*)d_in[1];
    const float* Xt   = (const float*)d_in[2];
    const int*   et   = (const int*)d_in[3];
    const int*   csrc = (const int*)d_in[6];
    const int*   cdst = (const int*)d_in[7];

    const float* W_ac_q = (const float*)d_in[10]; const float* b_ac_q = (const float*)d_in[11];
    const float* W_ac_t = (const float*)d_in[12]; const float* b_ac_t = (const float*)d_in[13];
    const float* W_vc_q = (const float*)d_in[14]; const float* b_vc_q = (const float*)d_in[15];
    const float* W_vc_t = (const float*)d_in[16]; const float* b_vc_t = (const float*)d_in[17];
    const float* W_mq   = (const float*)d_in[18]; const float* b_mq   = (const float*)d_in[19];
    const float* W_mt   = (const float*)d_in[20]; const float* b_mt   = (const float*)d_in[21];
    const float* W_aq   = (const float*)d_in[22]; const float* b_aq   = (const float*)d_in[23];
    const float* W_vq   = (const float*)d_in[24]; const float* b_vq   = (const float*)d_in[25];
    const float* W_at   = (const float*)d_in[26]; const float* b_at   = (const float*)d_in[27];
    const float* W_vt   = (const float*)d_in[28]; const float* b_vt   = (const float*)d_in[29];

    float* outQ = (float*)d_out;
    float* outT = outQ + SZ;

    __half* HQ_AC = (__half*)(S + O_HQ_AC);
    __half* HT_AC = (__half*)(S + O_HT_AC);
    __half* HQ_VC = (__half*)(S + O_HQ_VC);
    __half* HPS_T = (__half*)(S + O_HPS_T);
    __half* HPS_Q = (__half*)(S + O_HPS_Q);
    __half* WH    = (__half*)(S + O_WH);

    // zero-inits
    cudaMemsetAsync(S + O_SV,  0, (O_ZEND - O_SV) * sizeof(float), 0);
    cudaMemsetAsync(S + O_ACC, 0, SZ * sizeof(float), 0);
    cudaMemsetAsync(d_out,     0, 2 * SZ * sizeof(float), 0);

    // ---- weight pre-conversion (fp32 -> fp16) ----
    {
        CvBatch b;
        b.j[0] = {W_ac_q, WH + WH_ACQ, 16384};
        b.j[1] = {W_ac_t, WH + WH_ACT, 16384};
        b.j[2] = {W_vc_q, WH + WH_VCQ, 16384};
        b.j[3] = {W_vc_t, WH + WH_VCT, 16384};
        b.j[4] = {W_mq,   WH + WH_MQ,  32768};
        b.j[5] = {W_mt,   WH + WH_MT,  32768};
        b.j[6] = {W_vt,   WH + WH_VT,  32768};
        b.j[7] = {W_vq,   WH + WH_VQ,  32768};
        convert_w_b<<<dim3(32, 8), 256>>>(b);
    }

    // ---- stage 1: 4 ELU node transforms ----
    {
        GemmBatch b;
        b.j[0] = {Xq, nullptr, 128, 128, WH + WH_ACQ, b_ac_q, HQ_AC,       1, nullptr, 0, 1};
        b.j[1] = {Xt, nullptr, 128, 128, WH + WH_ACT, b_ac_t, HT_AC,       1, nullptr, 0, 1};
        b.j[2] = {Xq, nullptr, 128, 128, WH + WH_VCQ, b_vc_q, HQ_VC,       1, nullptr, 0, 1};
        b.j[3] = {Xt, nullptr, 128, 128, WH + WH_VCT, b_vc_t, S + O_XT_VC, 1, nullptr, 0, 0};
        hgemm_b<<<dim3(kNQ / 64, 4), 256>>>(b);
    }

    colsum_kernel<<<kNQ / 128, 128>>>(Xq, S + O_QSUM);
    bias_mt_kernel<<<1, 128>>>(S + O_QSUM, W_mt, b_mt, S + O_BIAS);

    // ---- fused cross attention ----
    cross_fused<<<(kEC / 4) * 32 / 256, 256>>>(csrc, cdst, HQ_AC, HT_AC, HQ_VC,
                                               S + O_SV, S + O_CNT, S + O_ACC);

    // ---- stage 2: merged features, K=256, normalization folded into A1 load ----
    {
        GemmBatch b;
        b.j[0] = {Xq, S + O_XT_VC, 128, 256, WH + WH_MQ, b_mq,       S + O_XQM, 0, S + O_CNT, 2, 0};
        b.j[1] = {Xt, S + O_ACC,   128, 256, WH + WH_MT, S + O_BIAS, S + O_XTM, 0, S + O_SV,  1, 0};
        b.j[2] = b.j[0]; b.j[3] = b.j[0];
        hgemm_b<<<dim3(kNQ / 64, 2), 256>>>(b);
    }

    // ---- stage 3: 4 intra projections ----
    {
        GemmBatch b;
        b.j[0] = {S + O_XTM, nullptr, 128, 128, WH + WH_VT,         nullptr, HPS_T,      0, nullptr, 0, 1};
        b.j[1] = {S + O_XTM, nullptr, 128, 128, WH + WH_VT + 16384, b_vt,    S + O_PD_T, 0, nullptr, 0, 0};
        b.j[2] = {S + O_XQM, nullptr, 128, 128, WH + WH_VQ,         nullptr, HPS_Q,      0, nullptr, 0, 1};
        b.j[3] = {S + O_XQM, nullptr, 128, 128, WH + WH_VQ + 16384, b_vq,    S + O_PD_Q, 0, nullptr, 0, 0};
        hgemm_b<<<dim3(kNQ / 64, 4), 256>>>(b);
    }

    {
        NsBatch b;
        b.j[0] = {S + O_XTM, W_at, b_at, S + O_SSRC_T, S + O_SDST_T};
        b.j[1] = {S + O_XQM, W_aq, b_aq, S + O_SSRC_Q, S + O_SDST_Q};
        node_scalars_b<<<dim3((kNT * 32) / 256, 2), 256>>>(b, kNT);
    }

    // ---- fused intra attention (both graphs in one launch) ----
    {
        IfBatch b;
        b.j[0] = {et, et + kET, S + O_SSRC_T, S + O_SDST_T, HPS_T, S + O_ST, outT};
        b.j[1] = {eq, eq + kEQ, S + O_SSRC_Q, S + O_SDST_Q, HPS_Q, S + O_SQ, outQ};
        intra_fused_b<<<dim3((kET / 4) * 32 / 256, 2), 256>>>(b, kET);
    }

    // ---- finalize: normalize + add dst projection ----
    {
        FinBatch b;
        b.j[0] = {S + O_ST, S + O_PD_T, outT};
        b.j[1] = {S + O_SQ, S + O_PD_Q, outQ};
        finalize_b<<<dim3(SZ / 4 / 256, 2), 256>>>(b);
    }
}

// round 12
// speedup vs baseline: 1.2748x; 1.0422x over previous
#include <cuda_runtime.h>
#include <cuda_fp16.h>
#include <math.h>

// Problem constants
constexpr int kNQ = 8192;
constexpr int kNT = 8192;
constexpr int kD  = 128;
constexpr int kEC = 262144;
constexpr int kEQ = 262144;
constexpr int kET = 262144;

constexpr size_t SZ = (size_t)kNQ * kD;

// ---- scratch layout (float slots) ----
constexpr size_t O_HQ_AC = 0;              // half Xq_ac
constexpr size_t O_HT_AC = 1*SZ;           // half Xt_ac
constexpr size_t O_HQ_VC = 2*SZ;           // half Xq_vc
constexpr size_t O_XT_VC = 3*SZ;           // fp32 Xt_vc
constexpr size_t O_ACC   = 4*SZ;           // unnormalized Xq2t accumulator (fp32)
constexpr size_t O_XQM   = 5*SZ;
constexpr size_t O_XTM   = 6*SZ;
constexpr size_t O_HPS_T = 7*SZ;           // half Ps_T
constexpr size_t O_PD_T  = 8*SZ;
constexpr size_t O_HPS_Q = 9*SZ;           // half Ps_Q
constexpr size_t O_PD_Q  = 10*SZ;
// zero-init scalar block
constexpr size_t O_SV    = 11*SZ;
constexpr size_t O_CNT   = O_SV + kNT;
constexpr size_t O_ST    = O_CNT + kNQ;
constexpr size_t O_SQ    = O_ST + kNT;
constexpr size_t O_QSUM  = O_SQ + kNQ;
constexpr size_t O_ZEND  = O_QSUM + kD;
// non-zeroed scalars
constexpr size_t O_SSRC_T= O_ZEND;
constexpr size_t O_SDST_T= O_SSRC_T + kNT;
constexpr size_t O_SSRC_Q= O_SDST_T + kNT;
constexpr size_t O_SDST_Q= O_SSRC_Q + kNQ;
constexpr size_t O_BIAS  = O_SDST_Q + kNQ;
// fp16 pre-converted weights (196608 halves = 98304 float slots)
constexpr size_t O_WH    = O_BIAS + kD;
constexpr size_t O_TOTAL = O_WH + 98304;

// half offsets inside the WH region
constexpr int WH_ACQ = 0;
constexpr int WH_ACT = 16384;
constexpr int WH_VCQ = 32768;
constexpr int WH_VCT = 49152;
constexpr int WH_MQ  = 65536;   // 256x128
constexpr int WH_MT  = 98304;   // 256x128 (rows 0-255 of W_mt)
constexpr int WH_VT  = 131072;  // 256x128
constexpr int WH_VQ  = 163840;  // 256x128

__device__ __align__(16) float g_scratch[O_TOTAL];

__device__ __forceinline__ float2 h2f(unsigned u) {
    __half2 h = *reinterpret_cast<__half2*>(&u);
    return __half22float2(h);
}

// ============================================================
// Tensor-core building blocks
// ============================================================
__device__ __forceinline__ void ldsm4(unsigned& r0, unsigned& r1, unsigned& r2, unsigned& r3,
                                      unsigned addr) {
    asm volatile("ldmatrix.sync.aligned.m8n8.x4.shared.b16 {%0,%1,%2,%3}, [%4];"
                 : "=r"(r0), "=r"(r1), "=r"(r2), "=r"(r3) : "r"(addr));
}
__device__ __forceinline__ void ldsm4t(unsigned& r0, unsigned& r1, unsigned& r2, unsigned& r3,
                                       unsigned addr) {
    asm volatile("ldmatrix.sync.aligned.m8n8.x4.trans.shared.b16 {%0,%1,%2,%3}, [%4];"
                 : "=r"(r0), "=r"(r1), "=r"(r2), "=r"(r3) : "r"(addr));
}
__device__ __forceinline__ void mma16816(float* c,
                                         unsigned a0, unsigned a1, unsigned a2, unsigned a3,
                                         unsigned b0, unsigned b1) {
    asm volatile("mma.sync.aligned.m16n8k16.row.col.f32.f16.f16.f32 "
                 "{%0,%1,%2,%3}, {%4,%5,%6,%7}, {%8,%9}, {%0,%1,%2,%3};"
                 : "+f"(c[0]), "+f"(c[1]), "+f"(c[2]), "+f"(c[3])
                 : "r"(a0), "r"(a1), "r"(a2), "r"(a3), "r"(b0), "r"(b1));
}
__device__ __forceinline__ void cp16(unsigned dst, const void* src) {
    asm volatile("cp.async.ca.shared.global [%0], [%1], 16;" :: "r"(dst), "l"(src));
}

// ============================================================
// Weight pre-conversion: fp32 -> fp16, batched jobs
// ============================================================
struct CvJob { const float* src; __half* dst; int n; };
struct CvBatch { CvJob j[8]; };
__global__ void convert_w_b(const __grid_constant__ CvBatch batch)
{
    const CvJob& J = batch.j[blockIdx.y];
    int i = (blockIdx.x * 256 + threadIdx.x) * 4;
    if (i >= J.n) return;
    float4 v = *reinterpret_cast<const float4*>(J.src + i);
    __half2 h0 = __floats2half2_rn(v.x, v.y);
    __half2 h1 = __floats2half2_rn(v.z, v.w);
    uint2 o = {*reinterpret_cast<unsigned*>(&h0), *reinterpret_cast<unsigned*>(&h1)};
    *reinterpret_cast<uint2*>(J.dst + i) = o;
}

// ============================================================
// Batched HMMA GEMM, double-buffered, BK=32, cp.async W staging.
// ============================================================
struct GemmJob {
    const float* A0; const float* A1;
    int K0; int K;
    const __half* W; const float* bias;
    void* C; int act;
    const float* s1; int smode;
    int outHalf;
};
struct GemmBatch { GemmJob j[4]; };

constexpr int PA = 40;    // halves per A smem row (32 + 8 pad)
constexpr int PW = 136;   // halves per W smem row (128 + 8 pad)
constexpr int ABUFB = 64 * PA * 2;
constexpr int WBUFB = 32 * PW * 2;

__global__ void hgemm_b(const __grid_constant__ GemmBatch batch)
{
    const GemmJob& J = batch.j[blockIdx.y];

    __shared__ __half Asm[2][64 * PA];
    __shared__ __half Wsm[2][32 * PW];

    const int tid  = threadIdx.x;
    const int lane = tid & 31;
    const int wid  = tid >> 5;
    const int wm   = wid >> 1;
    const int wn   = wid & 1;
    const int m0   = blockIdx.x * 64;
    const int g    = lane >> 2, t = lane & 3;

    float acc[8][4];
    #pragma unroll
    for (int j = 0; j < 8; j++)
        #pragma unroll
        for (int i = 0; i < 4; i++) acc[j][i] = 0.f;

    const unsigned aBase = (unsigned)__cvta_generic_to_shared(&Asm[0][0]);
    const unsigned wBase = (unsigned)__cvta_generic_to_shared(&Wsm[0][0]);
    const unsigned aOff = ((wm * 16 + (lane & 15)) * PA + ((lane >> 4) * 8)) << 1;
    const unsigned wOff = ((lane & 15) * PW + wn * 64 + ((lane >> 4) * 8)) << 1;

    const int arow = tid >> 2;
    const int acol = (tid & 3) * 8;
    const int wr0 = tid >> 4,          wc8_0 = (tid & 15) * 8;
    const int wr1 = (tid + 256) >> 4,  wc8_1 = wc8_0;

    const int K = J.K, K0 = J.K0;
    const int nc = K / 32;

    float4 ra0, ra1; float scale = 1.f;

    auto issueW = [&](int c, int buf) {
        const __half* ws = J.W + (size_t)(c * 32) * 128;
        unsigned wd = wBase + buf * WBUFB;
        cp16(wd + ((wr0 * PW + wc8_0) << 1), ws + wr0 * 128 + wc8_0);
        cp16(wd + ((wr1 * PW + wc8_1) << 1), ws + wr1 * 128 + wc8_1);
        asm volatile("cp.async.commit_group;");
    };
    auto ldgA = [&](int c) {
        int kc = c * 32;
        bool inA1 = (kc >= K0);
        const float* Ap = inA1 ? J.A1 : J.A0;
        int ldA = inA1 ? (K - K0) : K0;
        int kb  = inA1 ? (kc - K0) : kc;
        const float* src = Ap + (size_t)(m0 + arow) * ldA + kb + acol;
        ra0 = *reinterpret_cast<const float4*>(src);
        ra1 = *reinterpret_cast<const float4*>(src + 4);
        scale = 1.f;
        if (inA1 && J.smode) {
            float sv = J.s1[m0 + arow];
            scale = (J.smode == 1) ? (sv > 0.f ? 1.f / sv : 0.f)
                                   : (sv > 0.f ? 1.f : 0.f);
        }
    };
    auto stsA = [&](int buf) {
        __half2 h0 = __floats2half2_rn(ra0.x * scale, ra0.y * scale);
        __half2 h1 = __floats2half2_rn(ra0.z * scale, ra0.w * scale);
        __half2 h2 = __floats2half2_rn(ra1.x * scale, ra1.y * scale);
        __half2 h3 = __floats2half2_rn(ra1.z * scale, ra1.w * scale);
        uint4 o = {*reinterpret_cast<unsigned*>(&h0), *reinterpret_cast<unsigned*>(&h1),
                   *reinterpret_cast<unsigned*>(&h2), *reinterpret_cast<unsigned*>(&h3)};
        *reinterpret_cast<uint4*>(&Asm[buf][arow * PA + acol]) = o;
    };

    issueW(0, 0);
    ldgA(0);
    stsA(0);
    asm volatile("cp.async.wait_group 0;");
    __syncthreads();

    for (int c = 0; c < nc; c++) {
        int cur = c & 1, nxt = cur ^ 1;
        bool more = (c + 1 < nc);
        if (more) {
            issueW(c + 1, nxt);
            ldgA(c + 1);
        }
        unsigned aA = aBase + cur * ABUFB + aOff;
        unsigned wA = wBase + cur * WBUFB + wOff;
        #pragma unroll
        for (int ks = 0; ks < 2; ks++) {
            unsigned a0, a1, a2, a3;
            ldsm4(a0, a1, a2, a3, aA + ks * 32);
            #pragma unroll
            for (int nb = 0; nb < 4; nb++) {
                unsigned b0, b1, b2, b3;
                ldsm4t(b0, b1, b2, b3, wA + ((ks * 16 * PW + nb * 16) << 1));
                mma16816(acc[nb * 2],     a0, a1, a2, a3, b0, b1);
                mma16816(acc[nb * 2 + 1], a0, a1, a2, a3, b2, b3);
            }
        }
        if (more) {
            stsA(nxt);
            asm volatile("cp.async.wait_group 0;");
        }
        __syncthreads();
    }

    const int rowA = m0 + wm * 16 + g;
    #pragma unroll
    for (int j = 0; j < 8; j++) {
        int col = wn * 64 + (j >> 1) * 16 + (j & 1) * 8 + t * 2;
        float b0 = 0.f, b1 = 0.f;
        if (J.bias) { b0 = J.bias[col]; b1 = J.bias[col + 1]; }
        float v00 = acc[j][0] + b0, v01 = acc[j][1] + b1;
        float v10 = acc[j][2] + b0, v11 = acc[j][3] + b1;
        if (J.act) {
            v00 = v00 > 0.f ? v00 : expm1f(v00);
            v01 = v01 > 0.f ? v01 : expm1f(v01);
            v10 = v10 > 0.f ? v10 : expm1f(v10);
            v11 = v11 > 0.f ? v11 : expm1f(v11);
        }
        if (J.outHalf) {
            __half2 h0 = __floats2half2_rn(v00, v01);
            __half2 h1 = __floats2half2_rn(v10, v11);
            *reinterpret_cast<__half2*>((__half*)J.C + (size_t)rowA * 128 + col) = h0;
            *reinterpret_cast<__half2*>((__half*)J.C + (size_t)(rowA + 8) * 128 + col) = h1;
        } else {
            float2 f0 = {v00, v01}, f1 = {v10, v11};
            *reinterpret_cast<float2*>((float*)J.C + (size_t)rowA * 128 + col) = f0;
            *reinterpret_cast<float2*>((float*)J.C + (size_t)(rowA + 8) * 128 + col) = f1;
        }
    }
}

// column sums of Xq: 128 blocks x 64 rows each
__global__ void colsum_kernel(const float* __restrict__ X, float* __restrict__ sums)
{
    int j  = threadIdx.x;
    int r0 = blockIdx.x * 64;
    float s = 0.f;
    for (int r = 0; r < 64; r++) s += X[(size_t)(r0 + r) * kD + j];
    atomicAdd(&sums[j], s);
}

// be[j] = b_mt[j] + sum_k qsum[k]/NQ * W_mt[256+k, j]
// warp per output j (128 warps over 16 CTAs), lanes split k
__global__ void bias_mt_kernel(const float* __restrict__ qsum, const float* __restrict__ W_mt,
                               const float* __restrict__ b_mt, float* __restrict__ be)
{
    int j    = blockIdx.x * 8 + (threadIdx.x >> 5);   // 0..127
    int lane = threadIdx.x & 31;
    const float inv = 1.0f / (float)kNQ;
    float s = 0.f;
    #pragma unroll
    for (int i = 0; i < 4; i++) {
        int k = lane + i * 32;
        s = fmaf(qsum[k] * inv, W_mt[(size_t)(256 + k) * kD + j], s);
    }
    #pragma unroll
    for (int o = 16; o; o >>= 1) s += __shfl_xor_sync(0xffffffffu, s, o);
    if (lane == 0) be[j] = s + b_mt[j];
}

// ============================================================
// Fused cross attention (fp16 gathers, RED scatter)
// ============================================================
__global__ void cross_fused(const int* __restrict__ src, const int* __restrict__ dst,
                            const __half* __restrict__ Aq, const __half* __restrict__ At,
                            const __half* __restrict__ Vq,
                            float* __restrict__ s_v, float* __restrict__ cnt_u,
                            float* __restrict__ acc)
{
    int gtid = blockIdx.x * blockDim.x + threadIdx.x;
    int warp = gtid >> 5;
    int lane = gtid & 31;
    int e0 = warp * 4;

    int idxv = 0;
    if (lane < 8) {
        int e = e0 + (lane & 3);
        idxv = (lane < 4) ? src[e] : dst[e];
    }
    int uu[4], dd[4];
    #pragma unroll
    for (int k = 0; k < 4; k++) {
        uu[k] = __shfl_sync(0xffffffffu, idxv, k);
        dd[k] = __shfl_sync(0xffffffffu, idxv, 4 + k);
    }

    uint2 a[4], b[4], v[4];
    #pragma unroll
    for (int k = 0; k < 4; k++) {
        a[k] = *reinterpret_cast<const uint2*>(Aq + (size_t)uu[k] * kD + lane * 4);
        b[k] = *reinterpret_cast<const uint2*>(At + (size_t)dd[k] * kD + lane * 4);
        v[k] = *reinterpret_cast<const uint2*>(Vq + (size_t)uu[k] * kD + lane * 4);
    }

    float w[4];
    #pragma unroll
    for (int k = 0; k < 4; k++) {
        float2 a0 = h2f(a[k].x), a1 = h2f(a[k].y);
        float2 b0 = h2f(b[k].x), b1 = h2f(b[k].y);
        w[k] = a0.x * b0.x + a0.y * b0.y + a1.x * b1.x + a1.y * b1.y;
    }
    #pragma unroll
    for (int o = 16; o; o >>= 1) {
        #pragma unroll
        for (int k = 0; k < 4; k++) w[k] += __shfl_xor_sync(0xffffffffu, w[k], o);
    }
    #pragma unroll
    for (int k = 0; k < 4; k++) w[k] = expf(w[k]);

    {
        float wl = w[0]; int dl = dd[0], ul = uu[0];
        if (lane == 1) { wl = w[1]; dl = dd[1]; ul = uu[1]; }
        if (lane == 2) { wl = w[2]; dl = dd[2]; ul = uu[2]; }
        if (lane == 3) { wl = w[3]; dl = dd[3]; ul = uu[3]; }
        if (lane < 4) {
            atomicAdd(&s_v[dl], wl);
            atomicAdd(&cnt_u[ul], 1.0f);
        }
    }

    #pragma unroll
    for (int k = 0; k < 4; k++) {
        float2 v0 = h2f(v[k].x), v1 = h2f(v[k].y);
        float* p = acc + (size_t)dd[k] * kD + lane * 4;
        asm volatile("red.global.add.v4.f32 [%0], {%1,%2,%3,%4};"
                     :: "l"(p), "f"(w[k] * v0.x), "f"(w[k] * v0.y),
                        "f"(w[k] * v1.x), "f"(w[k] * v1.y)
                     : "memory");
    }
}

// batched per-node attention scalars (fp32 H)
struct NsJob { const float* H; const float* Wa; const float* ba; float* ssrc; float* sdst; };
struct NsBatch { NsJob j[2]; };
__global__ void node_scalars_b(const __grid_constant__ NsBatch batch, int N)
{
    const NsJob& J = batch.j[blockIdx.y];
    int idx  = blockIdx.x * blockDim.x + threadIdx.x;
    int n    = idx >> 5;
    int lane = idx & 31;
    if (n >= N) return;
    float4 h  = *reinterpret_cast<const float4*>(J.H  + (size_t)n * kD + lane * 4);
    float4 w0 = *reinterpret_cast<const float4*>(J.Wa + lane * 4);
    float4 w1 = *reinterpret_cast<const float4*>(J.Wa + 128 + lane * 4);
    float p0 = h.x * w0.x + h.y * w0.y + h.z * w0.z + h.w * w0.w;
    float p1 = h.x * w1.x + h.y * w1.y + h.z * w1.z + h.w * w1.w;
    #pragma unroll
    for (int o = 16; o; o >>= 1) {
        p0 += __shfl_xor_sync(0xffffffffu, p0, o);
        p1 += __shfl_xor_sync(0xffffffffu, p1, o);
    }
    if (lane == 0) { J.ssrc[n] = p0; J.sdst[n] = p1 + J.ba[0]; }
}

// ============================================================
// Fused intra attention, fp16 value gathers
// ============================================================
struct IfJob { const int* src; const int* dst; const float* ssrc; const float* sdst;
               const __half* Ps; float* s; float* out; };
struct IfBatch { IfJob j[2]; };
__global__ void intra_fused_b(const __grid_constant__ IfBatch batch, int E)
{
    const IfJob& J = batch.j[blockIdx.y];
    int gtid = blockIdx.x * blockDim.x + threadIdx.x;
    int warp = gtid >> 5;
    int lane = gtid & 31;
    int e0 = warp * 4;

    int sI = 0, dI = 0; float w = 0.f;
    if (lane < 4) {
        int e = e0 + lane;
        sI = J.src[e];
        dI = J.dst[e];
        w = expf(J.ssrc[sI] + J.sdst[dI]);
        atomicAdd(&J.s[dI], w);
    }

    int g[4], d[4]; float wk[4]; uint2 v[4];
    #pragma unroll
    for (int k = 0; k < 4; k++) {
        g[k]  = __shfl_sync(0xffffffffu, sI, k);
        d[k]  = __shfl_sync(0xffffffffu, dI, k);
        wk[k] = __shfl_sync(0xffffffffu, w,  k);
    }
    #pragma unroll
    for (int k = 0; k < 4; k++)
        v[k] = *reinterpret_cast<const uint2*>(J.Ps + (size_t)g[k] * kD + lane * 4);
    #pragma unroll
    for (int k = 0; k < 4; k++) {
        float2 v0 = h2f(v[k].x), v1 = h2f(v[k].y);
        float* p = J.out + (size_t)d[k] * kD + lane * 4;
        asm volatile("red.global.add.v4.f32 [%0], {%1,%2,%3,%4};"
                     :: "l"(p), "f"(wk[k] * v0.x), "f"(wk[k] * v0.y),
                        "f"(wk[k] * v1.x), "f"(wk[k] * v1.y)
                     : "memory");
    }
}

// batched finalize: out[n,:] = s[n] > 0 ? out[n,:]/s[n] + pd[n,:] : 0
struct FinJob { const float* s; const float* pd; float* out; };
struct FinBatch { FinJob j[2]; };
__global__ void finalize_b(const __grid_constant__ FinBatch batch)
{
    const FinJob& J = batch.j[blockIdx.y];
    size_t i4 = ((size_t)blockIdx.x * blockDim.x + threadIdx.x) * 4;
    int n = (int)(i4 >> 7);
    float sv = J.s[n];
    float4 o = *reinterpret_cast<float4*>(J.out + i4);
    float4 p = *reinterpret_cast<const float4*>(J.pd + i4);
    if (sv > 0.f) {
        float r = 1.f / sv;
        o.x = o.x * r + p.x;
        o.y = o.y * r + p.y;
        o.z = o.z * r + p.z;
        o.w = o.w * r + p.w;
    } else {
        o = {0.f, 0.f, 0.f, 0.f};
    }
    *reinterpret_cast<float4*>(J.out + i4) = o;
}

// ============================================================
extern "C" void kernel_launch(void* const* d_in, const int* in_sizes, int n_in,
                              void* d_out, int out_size)
{
    (void)in_sizes; (void)n_in; (void)out_size;
    float* S = nullptr;
    cudaGetSymbolAddress((void**)&S, g_scratch);

    const float* Xq   = (const float*)d_in[0];
    const int*   eq   = (const int*)d_in[1];
    const float* Xt   = (const float*)d_in[2];
    const int*   et   = (const int*)d_in[3];
    const int*   csrc = (const int*)d_in[6];
    const int*   cdst = (const int*)d_in[7];

    const float* W_ac_q = (const float*)d_in[10]; const float* b_ac_q = (const float*)d_in[11];
    const float* W_ac_t = (const float*)d_in[12]; const float* b_ac_t = (const float*)d_in[13];
    const float* W_vc_q = (const float*)d_in[14]; const float* b_vc_q = (const float*)d_in[15];
    const float* W_vc_t = (const float*)d_in[16]; const float* b_vc_t = (const float*)d_in[17];
    const float* W_mq   = (const float*)d_in[18]; const float* b_mq   = (const float*)d_in[19];
    const float* W_mt   = (const float*)d_in[20]; const float* b_mt   = (const float*)d_in[21];
    const float* W_aq   = (const float*)d_in[22]; const float* b_aq   = (const float*)d_in[23];
    const float* W_vq   = (const float*)d_in[24]; const float* b_vq   = (const float*)d_in[25];
    const float* W_at   = (const float*)d_in[26]; const float* b_at   = (const float*)d_in[27];
    const float* W_vt   = (const float*)d_in[28]; const float* b_vt   = (const float*)d_in[29];

    float* outQ = (float*)d_out;
    float* outT = outQ + SZ;

    __half* HQ_AC = (__half*)(S + O_HQ_AC);
    __half* HT_AC = (__half*)(S + O_HT_AC);
    __half* HQ_VC = (__half*)(S + O_HQ_VC);
    __half* HPS_T = (__half*)(S + O_HPS_T);
    __half* HPS_Q = (__half*)(S + O_HPS_Q);
    __half* WH    = (__half*)(S + O_WH);

    // zero-inits
    cudaMemsetAsync(S + O_SV,  0, (O_ZEND - O_SV) * sizeof(float), 0);
    cudaMemsetAsync(S + O_ACC, 0, SZ * sizeof(float), 0);
    cudaMemsetAsync(d_out,     0, 2 * SZ * sizeof(float), 0);

    // ---- weight pre-conversion (fp32 -> fp16) ----
    {
        CvBatch b;
        b.j[0] = {W_ac_q, WH + WH_ACQ, 16384};
        b.j[1] = {W_ac_t, WH + WH_ACT, 16384};
        b.j[2] = {W_vc_q, WH + WH_VCQ, 16384};
        b.j[3] = {W_vc_t, WH + WH_VCT, 16384};
        b.j[4] = {W_mq,   WH + WH_MQ,  32768};
        b.j[5] = {W_mt,   WH + WH_MT,  32768};
        b.j[6] = {W_vt,   WH + WH_VT,  32768};
        b.j[7] = {W_vq,   WH + WH_VQ,  32768};
        convert_w_b<<<dim3(32, 8), 256>>>(b);
    }

    // ---- stage 1: 4 ELU node transforms ----
    {
        GemmBatch b;
        b.j[0] = {Xq, nullptr, 128, 128, WH + WH_ACQ, b_ac_q, HQ_AC,       1, nullptr, 0, 1};
        b.j[1] = {Xt, nullptr, 128, 128, WH + WH_ACT, b_ac_t, HT_AC,       1, nullptr, 0, 1};
        b.j[2] = {Xq, nullptr, 128, 128, WH + WH_VCQ, b_vc_q, HQ_VC,       1, nullptr, 0, 1};
        b.j[3] = {Xt, nullptr, 128, 128, WH + WH_VCT, b_vc_t, S + O_XT_VC, 1, nullptr, 0, 0};
        hgemm_b<<<dim3(kNQ / 64, 4), 256>>>(b);
    }

    colsum_kernel<<<kNQ / 64, 128>>>(Xq, S + O_QSUM);
    bias_mt_kernel<<<16, 256>>>(S + O_QSUM, W_mt, b_mt, S + O_BIAS);

    // ---- fused cross attention ----
    cross_fused<<<(kEC / 4) * 32 / 256, 256>>>(csrc, cdst, HQ_AC, HT_AC, HQ_VC,
                                               S + O_SV, S + O_CNT, S + O_ACC);

    // ---- stage 2: merged features, K=256, normalization folded into A1 load ----
    {
        GemmBatch b;
        b.j[0] = {Xq, S + O_XT_VC, 128, 256, WH + WH_MQ, b_mq,       S + O_XQM, 0, S + O_CNT, 2, 0};
        b.j[1] = {Xt, S + O_ACC,   128, 256, WH + WH_MT, S + O_BIAS, S + O_XTM, 0, S + O_SV,  1, 0};
        b.j[2] = b.j[0]; b.j[3] = b.j[0];
        hgemm_b<<<dim3(kNQ / 64, 2), 256>>>(b);
    }

    // ---- stage 3: 4 intra projections ----
    {
        GemmBatch b;
        b.j[0] = {S + O_XTM, nullptr, 128, 128, WH + WH_VT,         nullptr, HPS_T,      0, nullptr, 0, 1};
        b.j[1] = {S + O_XTM, nullptr, 128, 128, WH + WH_VT + 16384, b_vt,    S + O_PD_T, 0, nullptr, 0, 0};
        b.j[2] = {S + O_XQM, nullptr, 128, 128, WH + WH_VQ,         nullptr, HPS_Q,      0, nullptr, 0, 1};
        b.j[3] = {S + O_XQM, nullptr, 128, 128, WH + WH_VQ + 16384, b_vq,    S + O_PD_Q, 0, nullptr, 0, 0};
        hgemm_b<<<dim3(kNQ / 64, 4), 256>>>(b);
    }

    {
        NsBatch b;
        b.j[0] = {S + O_XTM, W_at, b_at, S + O_SSRC_T, S + O_SDST_T};
        b.j[1] = {S + O_XQM, W_aq, b_aq, S + O_SSRC_Q, S + O_SDST_Q};
        node_scalars_b<<<dim3((kNT * 32) / 256, 2), 256>>>(b, kNT);
    }

    // ---- fused intra attention (both graphs in one launch) ----
    {
        IfBatch b;
        b.j[0] = {et, et + kET, S + O_SSRC_T, S + O_SDST_T, HPS_T, S + O_ST, outT};
        b.j[1] = {eq, eq + kEQ, S + O_SSRC_Q, S + O_SDST_Q, HPS_Q, S + O_SQ, outQ};
        intra_fused_b<<<dim3((kET / 4) * 32 / 256, 2), 256>>>(b, kET);
    }

    // ---- finalize: normalize + add dst projection ----
    {
        FinBatch b;
        b.j[0] = {S + O_ST, S + O_PD_T, outT};
        b.j[1] = {S + O_SQ, S + O_PD_Q, outQ};
        finalize_b<<<dim3(SZ / 4 / 256, 2), 256>>>(b);
    }
}